// round 3
// baseline (speedup 1.0000x reference)
#include <cuda_runtime.h>

#define NNODES 50000
#define NEDGES 600000
#define NRBF   50
#define DDIM   128
#define CUTOFF_F 5.0f
#define PI_F 3.14159265358979f

typedef unsigned long long ull;

// Scratch for segment_sum result (no cudaMalloc allowed)
__device__ float g_xint[NNODES * DDIM];

// ---------------- packed f32x2 helpers (Blackwell FFMA2 path) ----------------
__device__ __forceinline__ ull pack2(float a, float b) {
    ull r; asm("mov.b64 %0, {%1, %2};" : "=l"(r) : "f"(a), "f"(b)); return r;
}
__device__ __forceinline__ void unpack2(ull v, float& a, float& b) {
    asm("mov.b64 {%0, %1}, %2;" : "=f"(a), "=f"(b) : "l"(v));
}
__device__ __forceinline__ ull fma2(ull a, ull b, ull c) {
    ull d; asm("fma.rn.f32x2 %0, %1, %2, %3;" : "=l"(d) : "l"(a), "l"(b), "l"(c)); return d;
}
__device__ __forceinline__ ull add2(ull a, ull b) {
    ull d; asm("add.rn.f32x2 %0, %1, %2;" : "=l"(d) : "l"(a), "l"(b)); return d;
}
__device__ __forceinline__ ull mul2(ull a, ull b) {
    ull d; asm("mul.rn.f32x2 %0, %1, %2;" : "=l"(d) : "l"(a), "l"(b)); return d;
}

// ---------------------------------------------------------------------------
// Kernel 1: zero the scatter accumulator
// ---------------------------------------------------------------------------
__global__ void zero_kernel() {
    int i = blockIdx.x * blockDim.x + threadIdx.x;
    const int n = NNODES * DDIM / 4;
    float4* p = reinterpret_cast<float4*>(g_xint);
    float4 z = make_float4(0.f, 0.f, 0.f, 0.f);
    for (; i < n; i += gridDim.x * blockDim.x) p[i] = z;
}

// ---------------------------------------------------------------------------
// Kernel 2: edge stage.
// Lane layout (per warp): g = lane&15 -> dim group of 4 dims, khalf = lane>>4
// -> which half of the 50 RBF terms. Warp covers 64 dims; warps pair up
// (dhalf = wid&1) to cover all 128 dims of one edge.
// W_e held in registers: 4 dims x 25 terms = 100 regs/lane.
// Inner loop per r: 1 LDS.64 broadcast (pre-duplicated rbf) + 2 FFMA2.
// Scatter: one red.global.add.v4.f32 per 4 dims (16 active lanes/warp).
// ---------------------------------------------------------------------------
#define EPB 16  // edges staged per block-iteration

__global__ __launch_bounds__(128) void edge_kernel(
    const float* __restrict__ rbf,
    const float* __restrict__ dist,
    const int*   __restrict__ src,
    const int*   __restrict__ dst,
    const int*   __restrict__ node_type,
    const float* __restrict__ emb,
    const float* __restrict__ W_e,
    const float* __restrict__ b_e)
{
    __shared__ float2 rbf2_s[EPB * NRBF];  // duplicated pairs (v,v)
    __shared__ float  cut_s[EPB];
    __shared__ int    nt_s[EPB];
    __shared__ int    dst_s[EPB];

    const int t     = threadIdx.x;
    const int lane  = t & 31;
    const int wid   = t >> 5;
    const int dhalf = wid & 1;   // which 64-dim half
    const int epair = wid >> 1;  // warp-pair id (0/1) -> edge parity
    const int g     = lane & 15; // dim group
    const int khalf = lane >> 4; // rbf half
    const int d0    = dhalf * 64 + g * 4;
    const int r0    = khalf * 25;

    // Hoist this lane's W_e block into registers (loop-invariant)
    ull w2a[25], w2b[25];
#pragma unroll
    for (int i = 0; i < 25; ++i) {
        w2a[i] = pack2(W_e[(d0 + 0) * NRBF + r0 + i], W_e[(d0 + 1) * NRBF + r0 + i]);
        w2b[i] = pack2(W_e[(d0 + 2) * NRBF + r0 + i], W_e[(d0 + 3) * NRBF + r0 + i]);
    }
    const ull b2a = pack2(b_e[d0 + 0], b_e[d0 + 1]);
    const ull b2b = pack2(b_e[d0 + 2], b_e[d0 + 3]);

    const int stages = NEDGES / EPB;  // 37500, exact
    for (int s = blockIdx.x; s < stages; s += gridDim.x) {
        const int e0 = s * EPB;
        // Stage rbf rows as duplicated pairs + per-edge scalars
        for (int i = t; i < EPB * NRBF; i += 128) {
            const float v = rbf[e0 * NRBF + i];
            rbf2_s[i] = make_float2(v, v);
        }
        if (t < EPB) {
            const int e = e0 + t;
            const float dd = dist[e];
            cut_s[t] = (dd < CUTOFF_F) ? 0.5f * (cosf(dd * (PI_F / CUTOFF_F)) + 1.0f) : 0.0f;
            nt_s[t]  = node_type[src[e]];
            dst_s[t] = dst[e];
        }
        __syncthreads();

        for (int j = epair; j < EPB; j += 2) {
            const ull* rb = reinterpret_cast<const ull*>(rbf2_s + j * NRBF + r0);
            ull aa0 = 0, aa1 = 0, ab0 = 0, ab1 = 0;  // split dep chains
#pragma unroll
            for (int i = 0; i < 25; i += 2) {
                const ull r2 = rb[i];
                aa0 = fma2(r2, w2a[i], aa0);
                ab0 = fma2(r2, w2b[i], ab0);
            }
#pragma unroll
            for (int i = 1; i < 25; i += 2) {
                const ull r2 = rb[i];
                aa1 = fma2(r2, w2a[i], aa1);
                ab1 = fma2(r2, w2b[i], ab1);
            }
            ull aa = add2(aa0, aa1);
            ull ab = add2(ab0, ab1);
            // combine the two rbf-halves (partner lane = lane ^ 16)
            aa = add2(aa, __shfl_xor_sync(0xffffffffu, aa, 16));
            ab = add2(ab, __shfl_xor_sync(0xffffffffu, ab, 16));

            if (khalf == 0) {
                const float cut = cut_s[j];
                const ull c2 = pack2(cut, cut);
                const ull xe_a = mul2(add2(aa, b2a), c2);
                const ull xe_b = mul2(add2(ab, b2b), c2);
                const float4 xa4 = *reinterpret_cast<const float4*>(
                    emb + nt_s[j] * DDIM + d0);
                const ull m_a = mul2(pack2(xa4.x, xa4.y), xe_a);
                const ull m_b = mul2(pack2(xa4.z, xa4.w), xe_b);
                float f0, f1, f2, f3;
                unpack2(m_a, f0, f1);
                unpack2(m_b, f2, f3);
                float* p = g_xint + (size_t)dst_s[j] * DDIM + d0;
                asm volatile("red.global.add.v4.f32 [%0], {%1, %2, %3, %4};"
                             :: "l"(p), "f"(f0), "f"(f1), "f"(f2), "f"(f3)
                             : "memory");
            }
        }
        __syncthreads();
    }
}

// ---------------------------------------------------------------------------
// Kernel 3: combine — out[n][d] = b_c[d] + concat(x_nodes, g_xint)[n] . W_c[d]
// Thread t owns dim d=t. W_c in smem as b64 pairs, row stride 129 (conflict-
// free: bank8B = t*129+kp -> distinct mod 32). Packed over k-pairs: horizontal
// add at the end. NB nodes per iteration -> 8 FFMA2 per w-load.
// ---------------------------------------------------------------------------
#define NB 8
#define WP 129  // b64 stride per W row
#define COMBINE_SMEM ((DDIM * WP + NB * DDIM) * sizeof(ull))

__global__ __launch_bounds__(128) void combine_kernel(
    const float* __restrict__ x_nodes,
    const float* __restrict__ W_c,
    const float* __restrict__ b_c,
    float* __restrict__ out)
{
    extern __shared__ ull sm[];
    ull* W2  = sm;              // [128][129] b64
    ull* xr2 = sm + DDIM * WP;  // [NB][128]  b64 (= [NB][256] floats)

    const int t = threadIdx.x;

    // Stage full W_c (each row: 256 floats = 128 b64, contiguous in gmem)
    const ull* Wg = reinterpret_cast<const ull*>(W_c);
    for (int i = t; i < DDIM * 128; i += 128) {
        const int d = i >> 7, kp = i & 127;
        W2[d * WP + kp] = Wg[i];
    }
    const float bias = b_c[t];
    __syncthreads();

    const ull* wrow = W2 + t * WP;
    float4* xr4 = reinterpret_cast<float4*>(xr2);
    const float4* xn4 = reinterpret_cast<const float4*>(x_nodes);
    const float4* xi4 = reinterpret_cast<const float4*>(g_xint);

    const int iters = NNODES / NB;  // 6250, exact
    for (int it = blockIdx.x; it < iters; it += gridDim.x) {
        const int n0 = it * NB;
        // Stage NB concatenated rows: [x_nodes | g_xint], float4 moves
        for (int idx = t; idx < NB * 64; idx += 128) {
            const int j = idx >> 6, q = idx & 63;
            xr4[idx] = (q < 32) ? xn4[(n0 + j) * 32 + q]
                                : xi4[(n0 + j) * 32 + (q - 32)];
        }
        __syncthreads();

        ull acc[NB];
#pragma unroll
        for (int j = 0; j < NB; ++j) acc[j] = 0;

#pragma unroll 4
        for (int kp = 0; kp < 128; ++kp) {
            const ull w2 = wrow[kp];          // 1 LDS.64, conflict-free
#pragma unroll
            for (int j = 0; j < NB; ++j)      // 8 FFMA2 (xr reads broadcast)
                acc[j] = fma2(xr2[j * 128 + kp], w2, acc[j]);
        }
#pragma unroll
        for (int j = 0; j < NB; ++j) {
            float lo, hi;
            unpack2(acc[j], lo, hi);
            out[(n0 + j) * DDIM + t] = lo + hi + bias;
        }
        __syncthreads();
    }
}

// ---------------------------------------------------------------------------
// Launch. Inputs (metadata order):
//  0 node_type(i32)  1 x_nodes(f32)  2 src(i32)  3 dst(i32)  4 rbf_edges(f32)
//  5 dist(f32)       6 emb(f32)      7 W_e(f32)  8 b_e(f32)  9 W_c(f32) 10 b_c(f32)
// ---------------------------------------------------------------------------
extern "C" void kernel_launch(void* const* d_in, const int* in_sizes, int n_in,
                              void* d_out, int out_size) {
    const int*   node_type = (const int*)  d_in[0];
    const float* x_nodes   = (const float*)d_in[1];
    const int*   src       = (const int*)  d_in[2];
    const int*   dst       = (const int*)  d_in[3];
    const float* rbf       = (const float*)d_in[4];
    const float* dist      = (const float*)d_in[5];
    const float* emb       = (const float*)d_in[6];
    const float* W_e       = (const float*)d_in[7];
    const float* b_e       = (const float*)d_in[8];
    const float* W_c       = (const float*)d_in[9];
    const float* b_c       = (const float*)d_in[10];
    float* out = (float*)d_out;

    int sms = 148;
    cudaDeviceGetAttribute(&sms, cudaDevAttrMultiProcessorCount, 0);

    cudaFuncSetAttribute(combine_kernel,
                         cudaFuncAttributeMaxDynamicSharedMemorySize,
                         (int)COMBINE_SMEM);

    zero_kernel<<<512, 256>>>();
    edge_kernel<<<2048, 128>>>(rbf, dist, src, dst, node_type, emb, W_e, b_e);
    combine_kernel<<<sms, 128, COMBINE_SMEM>>>(x_nodes, W_c, b_c, out);
}

// round 5
// speedup vs baseline: 1.9874x; 1.9874x over previous
#include <cuda_runtime.h>

#define NNODES 50000
#define NEDGES 600000
#define NRBF   50
#define DDIM   128
#define CUTOFF_F 5.0f
#define PI_F 3.14159265358979f

// Scratch for segment_sum result (no cudaMalloc allowed)
__device__ float g_xint[NNODES * DDIM];

// ---------------------------------------------------------------------------
// Kernel 1: zero the scatter accumulator
// ---------------------------------------------------------------------------
__global__ void zero_kernel() {
    int i = blockIdx.x * blockDim.x + threadIdx.x;
    const int n = NNODES * DDIM / 4;
    float4* p = reinterpret_cast<float4*>(g_xint);
    float4 z = make_float4(0.f, 0.f, 0.f, 0.f);
    for (; i < n; i += gridDim.x * blockDim.x) p[i] = z;
}

// ---------------------------------------------------------------------------
// Kernel 2: edge stage (R2 structure + v4 scatter)
//   per edge e: xe[d] = (sum_r rbf[e][r]*W_e[d][r] + b_e[d]) * cutoff(dist[e])
//   msg[d]     = emb[node_type[src[e]]][d] * xe[d]   -> staged in smem
//   scatter    : red.global.add.v4.f32 into g_xint[dst[e]]
// blockDim=128, thread t owns dim d=t, W_e row in 50 registers.
// ---------------------------------------------------------------------------
#define EPB 8  // edges per block-stage

__global__ __launch_bounds__(128) void edge_kernel(
    const float* __restrict__ rbf,
    const float* __restrict__ dist,
    const int*   __restrict__ src,
    const int*   __restrict__ dst,
    const int*   __restrict__ node_type,
    const float* __restrict__ emb,
    const float* __restrict__ W_e,
    const float* __restrict__ b_e)
{
    __shared__ float rbf_s[EPB * NRBF];   // 400 floats (j*50*4B = 200j -> 8B aligned)
    __shared__ float msg_s[EPB * DDIM];   // 1024 floats
    __shared__ float cut_s[EPB];
    __shared__ int   nt_s[EPB];
    __shared__ int   dst_s[EPB];

    const int t = threadIdx.x;  // output dim

    // W_e row in registers (loop-invariant across edges)
    float wreg[NRBF];
#pragma unroll
    for (int r = 0; r < NRBF; ++r) wreg[r] = W_e[t * NRBF + r];
    const float bias = b_e[t];

    const int stages = NEDGES / EPB;  // 75000, exact
    for (int s = blockIdx.x; s < stages; s += gridDim.x) {
        const int e0 = s * EPB;
        // Stage rbf rows (coalesced) + per-edge scalars
        for (int i = t; i < EPB * NRBF; i += 128)
            rbf_s[i] = rbf[e0 * NRBF + i];
        if (t < EPB) {
            const int e = e0 + t;
            const float dd = dist[e];
            cut_s[t] = (dd < CUTOFF_F)
                         ? 0.5f * (cosf(dd * (PI_F / CUTOFF_F)) + 1.0f) : 0.0f;
            nt_s[t]  = node_type[src[e]];
            dst_s[t] = dst[e];
        }
        __syncthreads();

        // Compute phase: msg for all EPB edges -> smem
#pragma unroll
        for (int j = 0; j < EPB; ++j) {
            const float2* rb2 = reinterpret_cast<const float2*>(rbf_s + j * NRBF);
            float acc0 = bias, acc1 = 0.f;
#pragma unroll
            for (int r = 0; r < NRBF / 2; ++r) {
                const float2 v = rb2[r];        // LDS.64 broadcast
                acc0 += v.x * wreg[2 * r];
                acc1 += v.y * wreg[2 * r + 1];
            }
            const float xe = (acc0 + acc1) * cut_s[j];
            msg_s[j * DDIM + t] = emb[nt_s[j] * DDIM + t] * xe;
        }
        __syncthreads();

        // Scatter phase: EPB*32 float4 chunks, red.global.add.v4.f32
#pragma unroll
        for (int q = t; q < EPB * 32; q += 128) {
            const int j = q >> 5, c = q & 31;
            const float4 m = *reinterpret_cast<const float4*>(msg_s + j * DDIM + c * 4);
            float* p = g_xint + (size_t)dst_s[j] * DDIM + c * 4;
            asm volatile("red.global.add.v4.f32 [%0], {%1, %2, %3, %4};"
                         :: "l"(p), "f"(m.x), "f"(m.y), "f"(m.z), "f"(m.w)
                         : "memory");
        }
        __syncthreads();
    }
}

// ---------------------------------------------------------------------------
// Kernel 3: combine — out[n][d] = b_c[d] + concat(x_nodes, g_xint)[n] . W_c[d]
// 256 threads: d = t&127, node-group = t>>7 (8 nodes each; NB=16 per stage).
// W_c in smem [128][257] (conflict-free), 2 warps/SMSP keeps FMA pipe full.
// ---------------------------------------------------------------------------
#define NB 16
#define W_STRIDE 257
#define COMBINE_SMEM ((DDIM * W_STRIDE + NB * 2 * DDIM) * sizeof(float))

__global__ __launch_bounds__(256) void combine_kernel(
    const float* __restrict__ x_nodes,
    const float* __restrict__ W_c,
    const float* __restrict__ b_c,
    float* __restrict__ out)
{
    extern __shared__ float sm[];
    float* W_s = sm;                        // [128][257]
    float* xr  = sm + DDIM * W_STRIDE;      // [NB][256]

    const int t   = threadIdx.x;
    const int d   = t & 127;
    const int grp = t >> 7;                 // 0/1 -> nodes [grp*8, grp*8+8)

    // Stage full W_c once per block
    for (int i = t; i < DDIM * 2 * DDIM; i += 256) {
        const int dd = i >> 8, k = i & 255;
        W_s[dd * W_STRIDE + k] = W_c[i];
    }
    const float bias = b_c[d];
    __syncthreads();

    const float* wrow = W_s + d * W_STRIDE;
    float4* xr4 = reinterpret_cast<float4*>(xr);
    const float4* xn4 = reinterpret_cast<const float4*>(x_nodes);
    const float4* xi4 = reinterpret_cast<const float4*>(g_xint);

    const int iters = NNODES / NB;  // 3125, exact
    for (int it = blockIdx.x; it < iters; it += gridDim.x) {
        const int n0 = it * NB;
        // Stage NB concatenated rows [x_nodes | g_xint] as float4
        for (int idx = t; idx < NB * 64; idx += 256) {
            const int j = idx >> 6, q = idx & 63;
            xr4[idx] = (q < 32) ? xn4[(n0 + j) * 32 + q]
                                : xi4[(n0 + j) * 32 + (q - 32)];
        }
        __syncthreads();

        const float* xrg = xr + grp * 8 * 256;
        float acc[8];
#pragma unroll
        for (int j = 0; j < 8; ++j) acc[j] = bias;

#pragma unroll 4
        for (int k = 0; k < 2 * DDIM; ++k) {
            const float w = wrow[k];          // LDS conflict-free, broadcast in grp
#pragma unroll
            for (int j = 0; j < 8; ++j)       // 8 independent FFMA per LDS
                acc[j] += xrg[j * 256 + k] * w;
        }
#pragma unroll
        for (int j = 0; j < 8; ++j)
            out[(n0 + grp * 8 + j) * DDIM + d] = acc[j];
        __syncthreads();
    }
}

// ---------------------------------------------------------------------------
// Launch. Inputs (metadata order):
//  0 node_type(i32)  1 x_nodes(f32)  2 src(i32)  3 dst(i32)  4 rbf_edges(f32)
//  5 dist(f32)       6 emb(f32)      7 W_e(f32)  8 b_e(f32)  9 W_c(f32) 10 b_c(f32)
// ---------------------------------------------------------------------------
extern "C" void kernel_launch(void* const* d_in, const int* in_sizes, int n_in,
                              void* d_out, int out_size) {
    const int*   node_type = (const int*)  d_in[0];
    const float* x_nodes   = (const float*)d_in[1];
    const int*   src       = (const int*)  d_in[2];
    const int*   dst       = (const int*)  d_in[3];
    const float* rbf       = (const float*)d_in[4];
    const float* dist      = (const float*)d_in[5];
    const float* emb       = (const float*)d_in[6];
    const float* W_e       = (const float*)d_in[7];
    const float* b_e       = (const float*)d_in[8];
    const float* W_c       = (const float*)d_in[9];
    const float* b_c       = (const float*)d_in[10];
    float* out = (float*)d_out;

    int sms = 148;
    cudaDeviceGetAttribute(&sms, cudaDevAttrMultiProcessorCount, 0);

    cudaFuncSetAttribute(combine_kernel,
                         cudaFuncAttributeMaxDynamicSharedMemorySize,
                         (int)COMBINE_SMEM);

    zero_kernel<<<2048, 256>>>();
    edge_kernel<<<2048, 128>>>(rbf, dist, src, dst, node_type, emb, W_e, b_e);
    combine_kernel<<<sms, 256, COMBINE_SMEM>>>(x_nodes, W_c, b_c, out);
}

// round 7
// speedup vs baseline: 2.0521x; 1.0326x over previous
#include <cuda_runtime.h>
#include <cuda_bf16.h>
#include <cstdint>

#define NNODES 50000
#define NEDGES 600000
#define NRBF   50
#define DDIM   128
#define CUTOFF_F 5.0f
#define PI_F 3.14159265358979f

// Scratch for segment_sum result (no cudaMalloc allowed)
__device__ float g_xint[NNODES * DDIM];

// ---------------------------------------------------------------------------
__device__ __forceinline__ uint32_t smem_u32(const void* p) {
    uint32_t a;
    asm("{ .reg .u64 t; cvta.to.shared.u64 t, %1; cvt.u32.u64 %0, t; }"
        : "=r"(a) : "l"(p));
    return a;
}
__device__ __forceinline__ uint32_t swz128(uint32_t o) { return o ^ ((o >> 3) & 0x70); }

__device__ __forceinline__ void ldmatrix4(uint32_t r[4], uint32_t addr) {
    asm volatile("ldmatrix.sync.aligned.m8n8.x4.shared.b16 {%0,%1,%2,%3}, [%4];"
                 : "=r"(r[0]), "=r"(r[1]), "=r"(r[2]), "=r"(r[3]) : "r"(addr));
}
__device__ __forceinline__ void mma_bf16(float d[4], const uint32_t a[4],
                                         const uint32_t b[2]) {
    asm volatile("mma.sync.aligned.m16n8k16.row.col.f32.bf16.bf16.f32 "
                 "{%0,%1,%2,%3}, {%4,%5,%6,%7}, {%8,%9}, {%0,%1,%2,%3};"
                 : "+f"(d[0]), "+f"(d[1]), "+f"(d[2]), "+f"(d[3])
                 : "r"(a[0]), "r"(a[1]), "r"(a[2]), "r"(a[3]),
                   "r"(b[0]), "r"(b[1]));
}
__device__ __forceinline__ uint32_t pack_bf2(float x, float y) {
    __nv_bfloat162 h = __floats2bfloat162_rn(x, y);
    return *reinterpret_cast<uint32_t*>(&h);
}

// ---------------------------------------------------------------------------
// Kernel 1: zero the scatter accumulator
// ---------------------------------------------------------------------------
__global__ void zero_kernel() {
    int i = blockIdx.x * blockDim.x + threadIdx.x;
    const int n = NNODES * DDIM / 4;
    float4* p = reinterpret_cast<float4*>(g_xint);
    float4 z = make_float4(0.f, 0.f, 0.f, 0.f);
    for (; i < n; i += gridDim.x * blockDim.x) p[i] = z;
}

// ---------------------------------------------------------------------------
// Kernel 2: edge stage via mma.sync bf16 (hi/lo split, 3 passes).
// Tile = 128 edges x 128 dims, K = 64 (cols 0..49 rbf, col 50 = 1 -> bias).
// 256 threads = 8 warps; warp w owns dims [w*16, w*16+16).
// B = W_e split: kept in registers (2 ntiles x 4 ksteps x 2 regs x hi/lo).
// A staged in smem bf16 hi/lo, swizzled, read via ldmatrix.x4.
// D*cut -> msg smem (stride 132, conflict-free), then emb-mul + red.v4 scatter.
// ---------------------------------------------------------------------------
#define TILE_E 128
#define MSG_STRIDE 132
#define A_HI_OFF 0
#define A_LO_OFF 16384
#define MSG_OFF  32768                               // 128*132*4 = 67584
#define CUT_OFF  (MSG_OFF + TILE_E * MSG_STRIDE * 4) // 100352
#define DST_OFF  (CUT_OFF + 512)
#define NT_OFF   (DST_OFF + 512)
#define EDGE_SMEM (NT_OFF + 512)

__device__ __forceinline__ float we_elem(const float* W_e, const float* b_e,
                                         int d, int k) {
    if (k < NRBF) return W_e[d * NRBF + k];
    if (k == NRBF) return b_e[d];
    return 0.f;
}

__global__ __launch_bounds__(256) void edge_mma_kernel(
    const float* __restrict__ rbf,
    const float* __restrict__ dist,
    const int*   __restrict__ src,
    const int*   __restrict__ dst,
    const int*   __restrict__ node_type,
    const float* __restrict__ emb,
    const float* __restrict__ W_e,
    const float* __restrict__ b_e)
{
    extern __shared__ __align__(1024) char smem[];
    const uint32_t sb = smem_u32(smem);
    const int t    = threadIdx.x;
    const int lane = t & 31;
    const int wid  = t >> 5;

    float* msg_s = reinterpret_cast<float*>(smem + MSG_OFF);
    float* cut_s = reinterpret_cast<float*>(smem + CUT_OFF);
    int*   dst_s = reinterpret_cast<int*>(smem + DST_OFF);
    int*   nt_s  = reinterpret_cast<int*>(smem + NT_OFF);

    // Zero A tiles (cols >= 50 stay zero forever)
    {
        uint4* z4 = reinterpret_cast<uint4*>(smem);
        uint4 z = make_uint4(0, 0, 0, 0);
        for (int i = t; i < 32768 / 16; i += 256) z4[i] = z;
    }
    __syncthreads();
    // A col 50 = 1.0 in hi tile (bias lane), constant across tiles
    if (t < TILE_E) {
        *reinterpret_cast<uint32_t*>(smem + A_HI_OFF +
            swz128((uint32_t)(t * 128 + 100))) = pack_bf2(1.0f, 0.0f);
    }

    // Build B fragments in registers (persistent)
    uint32_t Bh[2][4][2], Bl[2][4][2];
#pragma unroll
    for (int n2 = 0; n2 < 2; ++n2) {
        const int d = wid * 16 + n2 * 8 + (lane >> 2);
#pragma unroll
        for (int ks = 0; ks < 4; ++ks) {
            const int k0 = ks * 16 + (lane & 3) * 2;
            float v[4];
            v[0] = we_elem(W_e, b_e, d, k0);
            v[1] = we_elem(W_e, b_e, d, k0 + 1);
            v[2] = we_elem(W_e, b_e, d, k0 + 8);
            v[3] = we_elem(W_e, b_e, d, k0 + 9);
            float h[4], l[4];
#pragma unroll
            for (int i = 0; i < 4; ++i) {
                h[i] = __bfloat162float(__float2bfloat16_rn(v[i]));
                l[i] = v[i] - h[i];
            }
            Bh[n2][ks][0] = pack_bf2(h[0], h[1]);
            Bh[n2][ks][1] = pack_bf2(h[2], h[3]);
            Bl[n2][ks][0] = pack_bf2(l[0], l[1]);
            Bl[n2][ks][1] = pack_bf2(l[2], l[3]);
        }
    }
    __syncthreads();

    const int ntiles = (NEDGES + TILE_E - 1) / TILE_E;  // 4688

    for (int tile = blockIdx.x; tile < ntiles; tile += gridDim.x) {
        // ---- stage per-edge scalars + A tile (hi/lo split, swizzled) ----
        if (t < TILE_E) {
            const int e = tile * TILE_E + t;
            float cut = 0.f; int nt = 0, dd = 0;
            if (e < NEDGES) {
                const float dis = dist[e];
                if (dis < CUTOFF_F)
                    cut = 0.5f * (__cosf(dis * (PI_F / CUTOFF_F)) + 1.0f);
                nt = node_type[src[e]];
                dd = dst[e];
            }
            cut_s[t] = cut; nt_s[t] = nt; dst_s[t] = dd;
        }
        for (int idx = t; idx < TILE_E * 25; idx += 256) {
            const int row = idx / 25, p = idx - row * 25;
            const int ee = tile * TILE_E + row;
            float2 v = make_float2(0.f, 0.f);
            if (ee < NEDGES)
                v = reinterpret_cast<const float2*>(rbf + (size_t)ee * NRBF)[p];
            const float hx = __bfloat162float(__float2bfloat16_rn(v.x));
            const float hy = __bfloat162float(__float2bfloat16_rn(v.y));
            const uint32_t sw = swz128((uint32_t)(row * 128 + p * 4));
            *reinterpret_cast<uint32_t*>(smem + A_HI_OFF + sw) = pack_bf2(hx, hy);
            *reinterpret_cast<uint32_t*>(smem + A_LO_OFF + sw) =
                pack_bf2(v.x - hx, v.y - hy);
        }
        __syncthreads();

        // ---- MMA phase: 8 m-blocks of 16 edges ----
        const int rowm = lane & 15;
        const int khb  = (lane >> 4) ? 16 : 0;  // bytes: +8 cols * 2B
#pragma unroll 1
        for (int mb = 0; mb < 8; ++mb) {
            uint32_t Ah[4][4], Al[4][4];
            const uint32_t rowbase = (uint32_t)((mb * 16 + rowm) * 128) + khb;
#pragma unroll
            for (int ks = 0; ks < 4; ++ks) {
                const uint32_t off = swz128(rowbase + ks * 32);
                ldmatrix4(Ah[ks], sb + A_HI_OFF + off);
                ldmatrix4(Al[ks], sb + A_LO_OFF + off);
            }
            float D[2][4] = {{0.f, 0.f, 0.f, 0.f}, {0.f, 0.f, 0.f, 0.f}};
#pragma unroll
            for (int n2 = 0; n2 < 2; ++n2) {
#pragma unroll
                for (int ks = 0; ks < 4; ++ks) {
                    mma_bf16(D[n2], Ah[ks], Bh[n2][ks]);
                    mma_bf16(D[n2], Ah[ks], Bl[n2][ks]);
                    mma_bf16(D[n2], Al[ks], Bh[n2][ks]);
                }
            }
            // write msg = D * cut to smem (conflict-free, stride 132)
            const int g  = lane >> 2, tq = lane & 3;
            const int r0 = mb * 16 + g;
            const float c0 = cut_s[r0], c8 = cut_s[r0 + 8];
#pragma unroll
            for (int n2 = 0; n2 < 2; ++n2) {
                const int col = wid * 16 + n2 * 8 + tq * 2;
                *reinterpret_cast<float2*>(msg_s + r0 * MSG_STRIDE + col) =
                    make_float2(D[n2][0] * c0, D[n2][1] * c0);
                *reinterpret_cast<float2*>(msg_s + (r0 + 8) * MSG_STRIDE + col) =
                    make_float2(D[n2][2] * c8, D[n2][3] * c8);
            }
        }
        __syncthreads();

        // ---- scatter: msg * emb[nt] -> red.global.add.v4 ----
#pragma unroll
        for (int q = t; q < TILE_E * 32; q += 256) {
            const int j = q >> 5, c = q & 31;
            if (cut_s[j] > 0.f) {
                const float4 m = *reinterpret_cast<const float4*>(
                    msg_s + j * MSG_STRIDE + c * 4);
                const float4 ev = reinterpret_cast<const float4*>(
                    emb + (size_t)nt_s[j] * DDIM)[c];
                float* p = g_xint + (size_t)dst_s[j] * DDIM + c * 4;
                asm volatile("red.global.add.v4.f32 [%0], {%1, %2, %3, %4};"
                             :: "l"(p), "f"(m.x * ev.x), "f"(m.y * ev.y),
                                "f"(m.z * ev.z), "f"(m.w * ev.w) : "memory");
            }
        }
        __syncthreads();
    }
}

// ---------------------------------------------------------------------------
// Kernel 3: combine — out[n][d] = b_c[d] + concat(x_nodes, g_xint)[n] . W_c[d]
// (unchanged: 256 thr, W_c smem [128][257], 8 nodes/thread)
// ---------------------------------------------------------------------------
#define NB 16
#define W_STRIDE 257
#define COMBINE_SMEM ((DDIM * W_STRIDE + NB * 2 * DDIM) * sizeof(float))

__global__ __launch_bounds__(256) void combine_kernel(
    const float* __restrict__ x_nodes,
    const float* __restrict__ W_c,
    const float* __restrict__ b_c,
    float* __restrict__ out)
{
    extern __shared__ float sm[];
    float* W_s = sm;
    float* xr  = sm + DDIM * W_STRIDE;

    const int t   = threadIdx.x;
    const int d   = t & 127;
    const int grp = t >> 7;

    for (int i = t; i < DDIM * 2 * DDIM; i += 256) {
        const int dd = i >> 8, k = i & 255;
        W_s[dd * W_STRIDE + k] = W_c[i];
    }
    const float bias = b_c[d];
    __syncthreads();

    const float* wrow = W_s + d * W_STRIDE;
    float4* xr4 = reinterpret_cast<float4*>(xr);
    const float4* xn4 = reinterpret_cast<const float4*>(x_nodes);
    const float4* xi4 = reinterpret_cast<const float4*>(g_xint);

    const int iters = NNODES / NB;
    for (int it = blockIdx.x; it < iters; it += gridDim.x) {
        const int n0 = it * NB;
        for (int idx = t; idx < NB * 64; idx += 256) {
            const int j = idx >> 6, q = idx & 63;
            xr4[idx] = (q < 32) ? xn4[(n0 + j) * 32 + q]
                                : xi4[(n0 + j) * 32 + (q - 32)];
        }
        __syncthreads();

        const float* xrg = xr + grp * 8 * 256;
        float acc[8];
#pragma unroll
        for (int j = 0; j < 8; ++j) acc[j] = bias;

#pragma unroll 4
        for (int k = 0; k < 2 * DDIM; ++k) {
            const float w = wrow[k];
#pragma unroll
            for (int j = 0; j < 8; ++j)
                acc[j] += xrg[j * 256 + k] * w;
        }
#pragma unroll
        for (int j = 0; j < 8; ++j)
            out[(n0 + grp * 8 + j) * DDIM + d] = acc[j];
        __syncthreads();
    }
}

// ---------------------------------------------------------------------------
// Launch. Inputs (metadata order):
//  0 node_type(i32)  1 x_nodes(f32)  2 src(i32)  3 dst(i32)  4 rbf_edges(f32)
//  5 dist(f32)       6 emb(f32)      7 W_e(f32)  8 b_e(f32)  9 W_c(f32) 10 b_c(f32)
// ---------------------------------------------------------------------------
extern "C" void kernel_launch(void* const* d_in, const int* in_sizes, int n_in,
                              void* d_out, int out_size) {
    const int*   node_type = (const int*)  d_in[0];
    const float* x_nodes   = (const float*)d_in[1];
    const int*   src       = (const int*)  d_in[2];
    const int*   dst       = (const int*)  d_in[3];
    const float* rbf       = (const float*)d_in[4];
    const float* dist      = (const float*)d_in[5];
    const float* emb       = (const float*)d_in[6];
    const float* W_e       = (const float*)d_in[7];
    const float* b_e       = (const float*)d_in[8];
    const float* W_c       = (const float*)d_in[9];
    const float* b_c       = (const float*)d_in[10];
    float* out = (float*)d_out;

    int sms = 148;
    cudaDeviceGetAttribute(&sms, cudaDevAttrMultiProcessorCount, 0);

    cudaFuncSetAttribute(edge_mma_kernel,
                         cudaFuncAttributeMaxDynamicSharedMemorySize, EDGE_SMEM);
    cudaFuncSetAttribute(combine_kernel,
                         cudaFuncAttributeMaxDynamicSharedMemorySize,
                         (int)COMBINE_SMEM);

    zero_kernel<<<2048, 256>>>();
    edge_mma_kernel<<<sms, 256, EDGE_SMEM>>>(rbf, dist, src, dst, node_type,
                                             emb, W_e, b_e);
    combine_kernel<<<sms, 256, COMBINE_SMEM>>>(x_nodes, W_c, b_c, out);
}

// round 8
// speedup vs baseline: 2.5897x; 1.2620x over previous
#include <cuda_runtime.h>
#include <cuda_bf16.h>
#include <cstdint>

#define NNODES 50000
#define NEDGES 600000
#define NRBF   50
#define DDIM   128
#define CUTOFF_F 5.0f
#define PI_F 3.14159265358979f
#define NBLK   196   // ceil(50000/256)

// __device__ scratch (no cudaMalloc allowed)
__device__ float g_xedge[NEDGES * DDIM];   // 307.2 MB: x_edge * cut, fp32
__device__ float g_xint[NNODES * DDIM];    // 25.6 MB: segment sum result
__device__ int   g_count[NNODES];
__device__ int   g_cursor[NNODES];
__device__ int   g_offset[NNODES + 1];
__device__ int   g_eid[NEDGES];
__device__ int   g_nt[NEDGES];
__device__ int   g_bsum[256];
__device__ int   g_bpre[256];

// ---------------------------------------------------------------------------
__device__ __forceinline__ uint32_t smem_u32(const void* p) {
    uint32_t a;
    asm("{ .reg .u64 t; cvta.to.shared.u64 t, %1; cvt.u32.u64 %0, t; }"
        : "=r"(a) : "l"(p));
    return a;
}
__device__ __forceinline__ uint32_t swz128(uint32_t o) { return o ^ ((o >> 3) & 0x70); }

__device__ __forceinline__ void ldmatrix4(uint32_t r[4], uint32_t addr) {
    asm volatile("ldmatrix.sync.aligned.m8n8.x4.shared.b16 {%0,%1,%2,%3}, [%4];"
                 : "=r"(r[0]), "=r"(r[1]), "=r"(r[2]), "=r"(r[3]) : "r"(addr));
}
__device__ __forceinline__ void mma_bf16(float d[4], const uint32_t a[4],
                                         const uint32_t b[2]) {
    asm volatile("mma.sync.aligned.m16n8k16.row.col.f32.bf16.bf16.f32 "
                 "{%0,%1,%2,%3}, {%4,%5,%6,%7}, {%8,%9}, {%0,%1,%2,%3};"
                 : "+f"(d[0]), "+f"(d[1]), "+f"(d[2]), "+f"(d[3])
                 : "r"(a[0]), "r"(a[1]), "r"(a[2]), "r"(a[3]),
                   "r"(b[0]), "r"(b[1]));
}
__device__ __forceinline__ uint32_t pack_bf2(float x, float y) {
    __nv_bfloat162 h = __floats2bfloat162_rn(x, y);
    return *reinterpret_cast<uint32_t*>(&h);
}

// ---------------------------------------------------------------------------
// Sort chain: histogram -> 3-step exclusive scan -> scatter edge ids
// ---------------------------------------------------------------------------
__global__ void zero_counts_kernel() {
    int i = blockIdx.x * blockDim.x + threadIdx.x;
    if (i < NNODES) g_count[i] = 0;
    if (i == 0) g_offset[NNODES] = NEDGES;
}

__global__ void hist_kernel(const int* __restrict__ dst,
                            const int* __restrict__ src,
                            const int* __restrict__ node_type) {
    int e = blockIdx.x * blockDim.x + threadIdx.x;
    if (e < NEDGES) {
        atomicAdd(&g_count[dst[e]], 1);
        g_nt[e] = node_type[src[e]];
    }
}

__global__ void scan_s1() {  // per-block sums of 256 counts
    __shared__ int sd[256];
    const int b = blockIdx.x, t = threadIdx.x;
    const int i = b * 256 + t;
    sd[t] = (i < NNODES) ? g_count[i] : 0;
    __syncthreads();
    for (int s = 128; s > 0; s >>= 1) {
        if (t < s) sd[t] += sd[t + s];
        __syncthreads();
    }
    if (t == 0) g_bsum[b] = sd[0];
}

__global__ void scan_s2() {  // exclusive scan of NBLK block sums (1 block)
    __shared__ int sc[256];
    const int t = threadIdx.x;
    sc[t] = (t < NBLK) ? g_bsum[t] : 0;
    __syncthreads();
    for (int off = 1; off < 256; off <<= 1) {
        int y = (t >= off) ? sc[t - off] : 0;
        __syncthreads();
        sc[t] += y;
        __syncthreads();
    }
    if (t < NBLK) g_bpre[t] = (t == 0) ? 0 : sc[t - 1];
}

__global__ void scan_s3() {  // write exclusive offsets + cursors
    __shared__ int sc[256];
    const int b = blockIdx.x, t = threadIdx.x;
    const int i = b * 256 + t;
    const int v = (i < NNODES) ? g_count[i] : 0;
    sc[t] = v;
    __syncthreads();
    for (int off = 1; off < 256; off <<= 1) {
        int y = (t >= off) ? sc[t - off] : 0;
        __syncthreads();
        sc[t] += y;
        __syncthreads();
    }
    if (i < NNODES) {
        const int excl = g_bpre[b] + sc[t] - v;
        g_offset[i] = excl;
        g_cursor[i] = excl;
    }
}

__global__ void scatter_sort_kernel(const int* __restrict__ dst) {
    int e = blockIdx.x * blockDim.x + threadIdx.x;
    if (e < NEDGES) {
        const int idx = atomicAdd(&g_cursor[dst[e]], 1);
        g_eid[idx] = e;
    }
}

// ---------------------------------------------------------------------------
// Edge GEMM (R7's proven mma.sync path): x_edge = (rbf@W_e^T + b_e)*cut,
// stored fp32 to g_xedge. No atomics.
// ---------------------------------------------------------------------------
#define TILE_E 128
#define MSG_STRIDE 132
#define A_HI_OFF 0
#define A_LO_OFF 16384
#define MSG_OFF  32768                                // 128*132*4 = 67584
#define CUT_OFF  (MSG_OFF + TILE_E * MSG_STRIDE * 4)  // 100352
#define EDGE_SMEM (CUT_OFF + 512)

__device__ __forceinline__ float we_elem(const float* W_e, const float* b_e,
                                         int d, int k) {
    if (k < NRBF) return W_e[d * NRBF + k];
    if (k == NRBF) return b_e[d];
    return 0.f;
}

__global__ __launch_bounds__(256) void edge_gemm_kernel(
    const float* __restrict__ rbf,
    const float* __restrict__ dist,
    const float* __restrict__ W_e,
    const float* __restrict__ b_e)
{
    extern __shared__ __align__(1024) char smem[];
    const uint32_t sb = smem_u32(smem);
    const int t    = threadIdx.x;
    const int lane = t & 31;
    const int wid  = t >> 5;

    float* msg_s = reinterpret_cast<float*>(smem + MSG_OFF);
    float* cut_s = reinterpret_cast<float*>(smem + CUT_OFF);

    // Zero A tiles (cols >= 51 stay zero forever)
    {
        uint4* z4 = reinterpret_cast<uint4*>(smem);
        uint4 z = make_uint4(0, 0, 0, 0);
        for (int i = t; i < 32768 / 16; i += 256) z4[i] = z;
    }
    __syncthreads();
    // A col 50 = 1.0 in hi tile (bias lane), constant across tiles
    if (t < TILE_E) {
        *reinterpret_cast<uint32_t*>(smem + A_HI_OFF +
            swz128((uint32_t)(t * 128 + 100))) = pack_bf2(1.0f, 0.0f);
    }

    // B = W_e hi/lo fragments in registers (persistent)
    uint32_t Bh[2][4][2], Bl[2][4][2];
#pragma unroll
    for (int n2 = 0; n2 < 2; ++n2) {
        const int d = wid * 16 + n2 * 8 + (lane >> 2);
#pragma unroll
        for (int ks = 0; ks < 4; ++ks) {
            const int k0 = ks * 16 + (lane & 3) * 2;
            float v[4];
            v[0] = we_elem(W_e, b_e, d, k0);
            v[1] = we_elem(W_e, b_e, d, k0 + 1);
            v[2] = we_elem(W_e, b_e, d, k0 + 8);
            v[3] = we_elem(W_e, b_e, d, k0 + 9);
            float h[4];
#pragma unroll
            for (int i = 0; i < 4; ++i)
                h[i] = __bfloat162float(__float2bfloat16_rn(v[i]));
            Bh[n2][ks][0] = pack_bf2(h[0], h[1]);
            Bh[n2][ks][1] = pack_bf2(h[2], h[3]);
            Bl[n2][ks][0] = pack_bf2(v[0] - h[0], v[1] - h[1]);
            Bl[n2][ks][1] = pack_bf2(v[2] - h[2], v[3] - h[3]);
        }
    }
    __syncthreads();

    const int ntiles = (NEDGES + TILE_E - 1) / TILE_E;  // 4688

    for (int tile = blockIdx.x; tile < ntiles; tile += gridDim.x) {
        // ---- stage cut + A tile (hi/lo split, swizzled) ----
        if (t < TILE_E) {
            const int e = tile * TILE_E + t;
            float cut = 0.f;
            if (e < NEDGES) {
                const float dis = dist[e];
                if (dis < CUTOFF_F)
                    cut = 0.5f * (__cosf(dis * (PI_F / CUTOFF_F)) + 1.0f);
            }
            cut_s[t] = cut;
        }
        for (int idx = t; idx < TILE_E * 25; idx += 256) {
            const int row = idx / 25, p = idx - row * 25;
            const int ee = tile * TILE_E + row;
            float2 v = make_float2(0.f, 0.f);
            if (ee < NEDGES)
                v = reinterpret_cast<const float2*>(rbf + (size_t)ee * NRBF)[p];
            const float hx = __bfloat162float(__float2bfloat16_rn(v.x));
            const float hy = __bfloat162float(__float2bfloat16_rn(v.y));
            const uint32_t sw = swz128((uint32_t)(row * 128 + p * 4));
            *reinterpret_cast<uint32_t*>(smem + A_HI_OFF + sw) = pack_bf2(hx, hy);
            *reinterpret_cast<uint32_t*>(smem + A_LO_OFF + sw) =
                pack_bf2(v.x - hx, v.y - hy);
        }
        __syncthreads();

        // ---- MMA: 8 m-blocks of 16 edges, 3 passes (hh, hl, lh) ----
        const int rowm = lane & 15;
        const int khb  = (lane >> 4) ? 16 : 0;
#pragma unroll 1
        for (int mb = 0; mb < 8; ++mb) {
            uint32_t Ah[4][4], Al[4][4];
            const uint32_t rowbase = (uint32_t)((mb * 16 + rowm) * 128) + khb;
#pragma unroll
            for (int ks = 0; ks < 4; ++ks) {
                const uint32_t off = swz128(rowbase + ks * 32);
                ldmatrix4(Ah[ks], sb + A_HI_OFF + off);
                ldmatrix4(Al[ks], sb + A_LO_OFF + off);
            }
            float D[2][4] = {{0.f, 0.f, 0.f, 0.f}, {0.f, 0.f, 0.f, 0.f}};
#pragma unroll
            for (int n2 = 0; n2 < 2; ++n2) {
#pragma unroll
                for (int ks = 0; ks < 4; ++ks) {
                    mma_bf16(D[n2], Ah[ks], Bh[n2][ks]);
                    mma_bf16(D[n2], Ah[ks], Bl[n2][ks]);
                    mma_bf16(D[n2], Al[ks], Bh[n2][ks]);
                }
            }
            const int g  = lane >> 2, tq = lane & 3;
            const int r0 = mb * 16 + g;
            const float c0 = cut_s[r0], c8 = cut_s[r0 + 8];
#pragma unroll
            for (int n2 = 0; n2 < 2; ++n2) {
                const int col = wid * 16 + n2 * 8 + tq * 2;
                *reinterpret_cast<float2*>(msg_s + r0 * MSG_STRIDE + col) =
                    make_float2(D[n2][0] * c0, D[n2][1] * c0);
                *reinterpret_cast<float2*>(msg_s + (r0 + 8) * MSG_STRIDE + col) =
                    make_float2(D[n2][2] * c8, D[n2][3] * c8);
            }
        }
        __syncthreads();

        // ---- store x_edge rows (coalesced float4 STG) ----
        float4* xe4 = reinterpret_cast<float4*>(g_xedge);
#pragma unroll
        for (int q = t; q < TILE_E * 32; q += 256) {
            const int j = q >> 5, c = q & 31;
            const int e = tile * TILE_E + j;
            if (e < NEDGES)
                xe4[(size_t)e * 32 + c] = *reinterpret_cast<const float4*>(
                    msg_s + j * MSG_STRIDE + c * 4);
        }
        __syncthreads();
    }
}

// ---------------------------------------------------------------------------
// Gather: warp per node, x_int[n] = sum_{e in CSR[n]} x_edge[e] * emb[nt[e]].
// No atomics; writes every node exactly once (zero_kernel unnecessary).
// ---------------------------------------------------------------------------
__global__ __launch_bounds__(256) void gather_kernel(const float* __restrict__ emb) {
    const int lane = threadIdx.x & 31;
    const int wid  = threadIdx.x >> 5;
    const int n = blockIdx.x * 8 + wid;
    if (n >= NNODES) return;

    const int beg = g_offset[n], end = g_offset[n + 1];
    const float4* xe4  = reinterpret_cast<const float4*>(g_xedge);
    const float4* emb4 = reinterpret_cast<const float4*>(emb);

    float4 acc = make_float4(0.f, 0.f, 0.f, 0.f);
    int i = beg;
    int e = 0, nt = 0;
    if (i < end) { e = g_eid[i]; nt = g_nt[e]; }  // uniform (broadcast) loads
    while (i < end) {
        const float4 xe = xe4[(size_t)e * 32 + lane];
        const float4 ev = emb4[(size_t)nt * 32 + lane];
        int e2 = 0, nt2 = 0;
        if (i + 1 < end) { e2 = g_eid[i + 1]; nt2 = g_nt[e2]; }  // prefetch
        acc.x += xe.x * ev.x;
        acc.y += xe.y * ev.y;
        acc.z += xe.z * ev.z;
        acc.w += xe.w * ev.w;
        e = e2; nt = nt2; ++i;
    }
    reinterpret_cast<float4*>(g_xint)[(size_t)n * 32 + lane] = acc;
}

// ---------------------------------------------------------------------------
// Combine (unchanged, proven): out[n][d] = b_c[d] + concat(x_nodes,x_int)[n].W_c[d]
// ---------------------------------------------------------------------------
#define NB 16
#define W_STRIDE 257
#define COMBINE_SMEM ((DDIM * W_STRIDE + NB * 2 * DDIM) * sizeof(float))

__global__ __launch_bounds__(256) void combine_kernel(
    const float* __restrict__ x_nodes,
    const float* __restrict__ W_c,
    const float* __restrict__ b_c,
    float* __restrict__ out)
{
    extern __shared__ float sm[];
    float* W_s = sm;
    float* xr  = sm + DDIM * W_STRIDE;

    const int t   = threadIdx.x;
    const int d   = t & 127;
    const int grp = t >> 7;

    for (int i = t; i < DDIM * 2 * DDIM; i += 256) {
        const int dd = i >> 8, k = i & 255;
        W_s[dd * W_STRIDE + k] = W_c[i];
    }
    const float bias = b_c[d];
    __syncthreads();

    const float* wrow = W_s + d * W_STRIDE;
    float4* xr4 = reinterpret_cast<float4*>(xr);
    const float4* xn4 = reinterpret_cast<const float4*>(x_nodes);
    const float4* xi4 = reinterpret_cast<const float4*>(g_xint);

    const int iters = NNODES / NB;
    for (int it = blockIdx.x; it < iters; it += gridDim.x) {
        const int n0 = it * NB;
        for (int idx = t; idx < NB * 64; idx += 256) {
            const int j = idx >> 6, q = idx & 63;
            xr4[idx] = (q < 32) ? xn4[(n0 + j) * 32 + q]
                                : xi4[(n0 + j) * 32 + (q - 32)];
        }
        __syncthreads();

        const float* xrg = xr + grp * 8 * 256;
        float acc[8];
#pragma unroll
        for (int j = 0; j < 8; ++j) acc[j] = bias;

#pragma unroll 4
        for (int k = 0; k < 2 * DDIM; ++k) {
            const float w = wrow[k];
#pragma unroll
            for (int j = 0; j < 8; ++j)
                acc[j] += xrg[j * 256 + k] * w;
        }
#pragma unroll
        for (int j = 0; j < 8; ++j)
            out[(n0 + grp * 8 + j) * DDIM + d] = acc[j];
        __syncthreads();
    }
}

// ---------------------------------------------------------------------------
// Launch. Inputs (metadata order):
//  0 node_type(i32)  1 x_nodes(f32)  2 src(i32)  3 dst(i32)  4 rbf_edges(f32)
//  5 dist(f32)       6 emb(f32)      7 W_e(f32)  8 b_e(f32)  9 W_c(f32) 10 b_c(f32)
// ---------------------------------------------------------------------------
extern "C" void kernel_launch(void* const* d_in, const int* in_sizes, int n_in,
                              void* d_out, int out_size) {
    const int*   node_type = (const int*)  d_in[0];
    const float* x_nodes   = (const float*)d_in[1];
    const int*   src       = (const int*)  d_in[2];
    const int*   dst       = (const int*)  d_in[3];
    const float* rbf       = (const float*)d_in[4];
    const float* dist      = (const float*)d_in[5];
    const float* emb       = (const float*)d_in[6];
    const float* W_e       = (const float*)d_in[7];
    const float* b_e       = (const float*)d_in[8];
    const float* W_c       = (const float*)d_in[9];
    const float* b_c       = (const float*)d_in[10];
    float* out = (float*)d_out;

    int sms = 148;
    cudaDeviceGetAttribute(&sms, cudaDevAttrMultiProcessorCount, 0);

    cudaFuncSetAttribute(edge_gemm_kernel,
                         cudaFuncAttributeMaxDynamicSharedMemorySize, EDGE_SMEM);
    cudaFuncSetAttribute(combine_kernel,
                         cudaFuncAttributeMaxDynamicSharedMemorySize,
                         (int)COMBINE_SMEM);

    const int eb = (NEDGES + 511) / 512;  // 1172

    zero_counts_kernel<<<(NNODES + 511) / 512, 512>>>();
    hist_kernel<<<eb, 512>>>(dst, src, node_type);
    scan_s1<<<NBLK, 256>>>();
    scan_s2<<<1, 256>>>();
    scan_s3<<<NBLK, 256>>>();
    scatter_sort_kernel<<<eb, 512>>>(dst);
    edge_gemm_kernel<<<2 * sms, 256, EDGE_SMEM>>>(rbf, dist, W_e, b_e);
    gather_kernel<<<(NNODES + 7) / 8, 256>>>(emb);
    combine_kernel<<<sms, 256, COMBINE_SMEM>>>(x_nodes, W_c, b_c, out);
}

// round 9
// speedup vs baseline: 2.7122x; 1.0473x over previous
#include <cuda_runtime.h>
#include <cuda_bf16.h>
#include <cstdint>

#define NNODES 50000
#define NEDGES 600000
#define NRBF   50
#define DDIM   128
#define CUTOFF_F 5.0f
#define PI_F 3.14159265358979f
#define NBLK   196   // ceil(50000/256)

// __device__ scratch (no cudaMalloc allowed)
__device__ float g_xint[NNODES * DDIM];    // 25.6 MB segment-sum result
__device__ int   g_count[NNODES];
__device__ int   g_cursor[NNODES];
__device__ int   g_nt[NEDGES];
__device__ int4  g_sedge[NEDGES];          // sorted-by-dst: {eid, dst, nt, 0}
__device__ int   g_bsum[256];
__device__ int   g_bpre[256];

// ---------------------------------------------------------------------------
__device__ __forceinline__ uint32_t smem_u32(const void* p) {
    uint32_t a;
    asm("{ .reg .u64 t; cvta.to.shared.u64 t, %1; cvt.u32.u64 %0, t; }"
        : "=r"(a) : "l"(p));
    return a;
}
__device__ __forceinline__ uint32_t swz128(uint32_t o) { return o ^ ((o >> 3) & 0x70); }

__device__ __forceinline__ void ldmatrix4(uint32_t r[4], uint32_t addr) {
    asm volatile("ldmatrix.sync.aligned.m8n8.x4.shared.b16 {%0,%1,%2,%3}, [%4];"
                 : "=r"(r[0]), "=r"(r[1]), "=r"(r[2]), "=r"(r[3]) : "r"(addr));
}
__device__ __forceinline__ void mma_bf16(float d[4], const uint32_t a[4],
                                         const uint32_t b[2]) {
    asm volatile("mma.sync.aligned.m16n8k16.row.col.f32.bf16.bf16.f32 "
                 "{%0,%1,%2,%3}, {%4,%5,%6,%7}, {%8,%9}, {%0,%1,%2,%3};"
                 : "+f"(d[0]), "+f"(d[1]), "+f"(d[2]), "+f"(d[3])
                 : "r"(a[0]), "r"(a[1]), "r"(a[2]), "r"(a[3]),
                   "r"(b[0]), "r"(b[1]));
}
__device__ __forceinline__ uint32_t pack_bf2(float x, float y) {
    __nv_bfloat162 h = __floats2bfloat162_rn(x, y);
    return *reinterpret_cast<uint32_t*>(&h);
}

// ---------------------------------------------------------------------------
// Zero g_xint (atomic target)
// ---------------------------------------------------------------------------
__global__ void zero_xint_kernel() {
    int i = blockIdx.x * blockDim.x + threadIdx.x;
    const int n = NNODES * DDIM / 4;
    float4* p = reinterpret_cast<float4*>(g_xint);
    float4 z = make_float4(0.f, 0.f, 0.f, 0.f);
    for (; i < n; i += gridDim.x * blockDim.x) p[i] = z;
}

// ---------------------------------------------------------------------------
// Sort chain: histogram -> 3-step exclusive scan -> scatter sorted records
// ---------------------------------------------------------------------------
__global__ void zero_counts_kernel() {
    int i = blockIdx.x * blockDim.x + threadIdx.x;
    if (i < NNODES) g_count[i] = 0;
}

__global__ void hist_kernel(const int* __restrict__ dst,
                            const int* __restrict__ src,
                            const int* __restrict__ node_type) {
    int e = blockIdx.x * blockDim.x + threadIdx.x;
    if (e < NEDGES) {
        atomicAdd(&g_count[dst[e]], 1);
        g_nt[e] = node_type[src[e]];
    }
}

__global__ void scan_s1() {
    __shared__ int sd[256];
    const int b = blockIdx.x, t = threadIdx.x;
    const int i = b * 256 + t;
    sd[t] = (i < NNODES) ? g_count[i] : 0;
    __syncthreads();
    for (int s = 128; s > 0; s >>= 1) {
        if (t < s) sd[t] += sd[t + s];
        __syncthreads();
    }
    if (t == 0) g_bsum[b] = sd[0];
}

__global__ void scan_s2() {
    __shared__ int sc[256];
    const int t = threadIdx.x;
    sc[t] = (t < NBLK) ? g_bsum[t] : 0;
    __syncthreads();
    for (int off = 1; off < 256; off <<= 1) {
        int y = (t >= off) ? sc[t - off] : 0;
        __syncthreads();
        sc[t] += y;
        __syncthreads();
    }
    if (t < NBLK) g_bpre[t] = (t == 0) ? 0 : sc[t - 1];
}

__global__ void scan_s3() {
    __shared__ int sc[256];
    const int b = blockIdx.x, t = threadIdx.x;
    const int i = b * 256 + t;
    const int v = (i < NNODES) ? g_count[i] : 0;
    sc[t] = v;
    __syncthreads();
    for (int off = 1; off < 256; off <<= 1) {
        int y = (t >= off) ? sc[t - off] : 0;
        __syncthreads();
        sc[t] += y;
        __syncthreads();
    }
    if (i < NNODES) g_cursor[i] = g_bpre[b] + sc[t] - v;
}

__global__ void scatter_sort_kernel(const int* __restrict__ dst) {
    int e = blockIdx.x * blockDim.x + threadIdx.x;
    if (e < NEDGES) {
        const int d = dst[e];
        const int idx = atomicAdd(&g_cursor[d], 1);
        g_sedge[idx] = make_int4(e, d, g_nt[e], 0);
    }
}

// ---------------------------------------------------------------------------
// Fused edge kernel: GEMM over sorted edges + segmented reduction + per-
// segment red.global.add.v4. No x_edge intermediate.
// ---------------------------------------------------------------------------
#define TILE_E 128
#define MSG_STRIDE 132
#define A_HI_OFF 0
#define A_LO_OFF 16384
#define MSG_OFF  32768                                // 128*132*4 = 67584
#define CUT_OFF  (MSG_OFF + TILE_E * MSG_STRIDE * 4)  // 100352
#define EID_OFF  (CUT_OFF + 512)
#define DST_OFF  (EID_OFF + 512)
#define NTS_OFF  (DST_OFF + 512)
#define SEG_OFF  (NTS_OFF + 512)
#define WTOT_OFF (SEG_OFF + 512)
#define EDGE_SMEM (WTOT_OFF + 64)

__device__ __forceinline__ float we_elem(const float* W_e, const float* b_e,
                                         int d, int k) {
    if (k < NRBF) return W_e[d * NRBF + k];
    if (k == NRBF) return b_e[d];
    return 0.f;
}

__global__ __launch_bounds__(256) void fused_edge_kernel(
    const float* __restrict__ rbf,
    const float* __restrict__ dist,
    const float* __restrict__ emb,
    const float* __restrict__ W_e,
    const float* __restrict__ b_e)
{
    extern __shared__ __align__(1024) char smem[];
    const uint32_t sb = smem_u32(smem);
    const int t    = threadIdx.x;
    const int lane = t & 31;
    const int wid  = t >> 5;

    float* msg_s  = reinterpret_cast<float*>(smem + MSG_OFF);
    float* cut_s  = reinterpret_cast<float*>(smem + CUT_OFF);
    int*   eid_s  = reinterpret_cast<int*>(smem + EID_OFF);
    int*   dst_s  = reinterpret_cast<int*>(smem + DST_OFF);
    int*   nts_s  = reinterpret_cast<int*>(smem + NTS_OFF);
    int*   seg_s  = reinterpret_cast<int*>(smem + SEG_OFF);
    int*   wtot_s = reinterpret_cast<int*>(smem + WTOT_OFF);

    // Zero A tiles (cols >= 51 stay zero forever)
    {
        uint4* z4 = reinterpret_cast<uint4*>(smem);
        uint4 z = make_uint4(0, 0, 0, 0);
        for (int i = t; i < 32768 / 16; i += 256) z4[i] = z;
    }
    __syncthreads();
    // A col 50 = 1.0 in hi tile (bias lane), constant across tiles
    if (t < TILE_E) {
        *reinterpret_cast<uint32_t*>(smem + A_HI_OFF +
            swz128((uint32_t)(t * 128 + 100))) = pack_bf2(1.0f, 0.0f);
    }

    // B = W_e hi/lo fragments in registers (persistent, proven layout)
    uint32_t Bh[2][4][2], Bl[2][4][2];
#pragma unroll
    for (int n2 = 0; n2 < 2; ++n2) {
        const int d = wid * 16 + n2 * 8 + (lane >> 2);
#pragma unroll
        for (int ks = 0; ks < 4; ++ks) {
            const int k0 = ks * 16 + (lane & 3) * 2;
            float v[4];
            v[0] = we_elem(W_e, b_e, d, k0);
            v[1] = we_elem(W_e, b_e, d, k0 + 1);
            v[2] = we_elem(W_e, b_e, d, k0 + 8);
            v[3] = we_elem(W_e, b_e, d, k0 + 9);
            float h[4];
#pragma unroll
            for (int i = 0; i < 4; ++i)
                h[i] = __bfloat162float(__float2bfloat16_rn(v[i]));
            Bh[n2][ks][0] = pack_bf2(h[0], h[1]);
            Bh[n2][ks][1] = pack_bf2(h[2], h[3]);
            Bl[n2][ks][0] = pack_bf2(v[0] - h[0], v[1] - h[1]);
            Bl[n2][ks][1] = pack_bf2(v[2] - h[2], v[3] - h[3]);
        }
    }
    __syncthreads();

    const int ntiles = (NEDGES + TILE_E - 1) / TILE_E;  // 4688
    const float4* emb4 = reinterpret_cast<const float4*>(emb);

    for (int tile = blockIdx.x; tile < ntiles; tile += gridDim.x) {
        const int i0 = tile * TILE_E;

        // ---- stage sorted records + cut ----
        if (t < TILE_E) {
            const int i = i0 + t;
            int e = -1, d = -1, nt = 0;
            float cut = 0.f;
            if (i < NEDGES) {
                const int4 v = g_sedge[i];
                e = v.x; d = v.y; nt = v.z;
                const float dis = dist[e];
                if (dis < CUTOFF_F)
                    cut = 0.5f * (__cosf(dis * (PI_F / CUTOFF_F)) + 1.0f);
            }
            eid_s[t] = e; dst_s[t] = d; nts_s[t] = nt; cut_s[t] = cut;
        }
        __syncthreads();

        // ---- stage A tile: gathered rbf rows, hi/lo split, swizzled ----
        for (int idx = t; idx < TILE_E * 25; idx += 256) {
            const int row = idx / 25, p = idx - row * 25;
            const int e = eid_s[row];
            float2 v = make_float2(0.f, 0.f);
            if (e >= 0)
                v = reinterpret_cast<const float2*>(rbf + (size_t)e * NRBF)[p];
            const float hx = __bfloat162float(__float2bfloat16_rn(v.x));
            const float hy = __bfloat162float(__float2bfloat16_rn(v.y));
            const uint32_t sw = swz128((uint32_t)(row * 128 + p * 4));
            *reinterpret_cast<uint32_t*>(smem + A_HI_OFF + sw) = pack_bf2(hx, hy);
            *reinterpret_cast<uint32_t*>(smem + A_LO_OFF + sw) =
                pack_bf2(v.x - hx, v.y - hy);
        }
        __syncthreads();

        // ---- MMA: 8 m-blocks of 16 edges, 3 passes (hh, hl, lh) ----
        const int rowm = lane & 15;
        const int khb  = (lane >> 4) ? 16 : 0;
#pragma unroll 1
        for (int mb = 0; mb < 8; ++mb) {
            uint32_t Ah[4][4], Al[4][4];
            const uint32_t rowbase = (uint32_t)((mb * 16 + rowm) * 128) + khb;
#pragma unroll
            for (int ks = 0; ks < 4; ++ks) {
                const uint32_t off = swz128(rowbase + ks * 32);
                ldmatrix4(Ah[ks], sb + A_HI_OFF + off);
                ldmatrix4(Al[ks], sb + A_LO_OFF + off);
            }
            float D[2][4] = {{0.f, 0.f, 0.f, 0.f}, {0.f, 0.f, 0.f, 0.f}};
#pragma unroll
            for (int n2 = 0; n2 < 2; ++n2) {
#pragma unroll
                for (int ks = 0; ks < 4; ++ks) {
                    mma_bf16(D[n2], Ah[ks], Bh[n2][ks]);
                    mma_bf16(D[n2], Ah[ks], Bl[n2][ks]);
                    mma_bf16(D[n2], Al[ks], Bh[n2][ks]);
                }
            }
            const int g  = lane >> 2, tq = lane & 3;
            const int r0 = mb * 16 + g;
            const float c0 = cut_s[r0], c8 = cut_s[r0 + 8];
#pragma unroll
            for (int n2 = 0; n2 < 2; ++n2) {
                const int col = wid * 16 + n2 * 8 + tq * 2;
                *reinterpret_cast<float2*>(msg_s + r0 * MSG_STRIDE + col) =
                    make_float2(D[n2][0] * c0, D[n2][1] * c0);
                *reinterpret_cast<float2*>(msg_s + (r0 + 8) * MSG_STRIDE + col) =
                    make_float2(D[n2][2] * c8, D[n2][3] * c8);
            }
        }

        // ---- build segments of equal dst (ballot scan over 128 rows) ----
        int flag = 0;
        if (t < TILE_E)
            flag = (t == 0) || (dst_s[t] != dst_s[t - 1]);
        const unsigned bits = __ballot_sync(0xffffffffu, flag);
        if (t < TILE_E && lane == 0) wtot_s[wid] = __popc(bits);
        __syncthreads();
        if (t < TILE_E) {
            int base = 0;
#pragma unroll
            for (int w = 0; w < 4; ++w) base += (w < wid) ? wtot_s[w] : 0;
            if (flag) {
                const unsigned le = (lane == 31) ? 0xffffffffu
                                                 : ((1u << (lane + 1)) - 1u);
                seg_s[base + __popc(bits & le) - 1] = t;
            }
        }
        __syncthreads();
        const int nseg = wtot_s[0] + wtot_s[1] + wtot_s[2] + wtot_s[3];

        // ---- segmented sum + one red.v4 per segment per lane ----
        for (int s = wid; s < nseg; s += 8) {
            const int a = seg_s[s];
            const int b = (s + 1 < nseg) ? seg_s[s + 1] : TILE_E;
            const int dv = dst_s[a];
            if (dv < 0) continue;
            float4 acc = make_float4(0.f, 0.f, 0.f, 0.f);
            for (int j = a; j < b; ++j) {
                const float4 m = *reinterpret_cast<const float4*>(
                    msg_s + j * MSG_STRIDE + lane * 4);
                const float4 ev = emb4[(size_t)nts_s[j] * 32 + lane];
                acc.x += m.x * ev.x;
                acc.y += m.y * ev.y;
                acc.z += m.z * ev.z;
                acc.w += m.w * ev.w;
            }
            float* p = g_xint + (size_t)dv * DDIM + lane * 4;
            asm volatile("red.global.add.v4.f32 [%0], {%1, %2, %3, %4};"
                         :: "l"(p), "f"(acc.x), "f"(acc.y),
                            "f"(acc.z), "f"(acc.w) : "memory");
        }
        __syncthreads();
    }
}

// ---------------------------------------------------------------------------
// Combine (unchanged, proven): out[n][d] = b_c[d] + concat(x_nodes,x_int)[n].W_c[d]
// ---------------------------------------------------------------------------
#define NB 16
#define W_STRIDE 257
#define COMBINE_SMEM ((DDIM * W_STRIDE + NB * 2 * DDIM) * sizeof(float))

__global__ __launch_bounds__(256) void combine_kernel(
    const float* __restrict__ x_nodes,
    const float* __restrict__ W_c,
    const float* __restrict__ b_c,
    float* __restrict__ out)
{
    extern __shared__ float sm[];
    float* W_s = sm;
    float* xr  = sm + DDIM * W_STRIDE;

    const int t   = threadIdx.x;
    const int d   = t & 127;
    const int grp = t >> 7;

    for (int i = t; i < DDIM * 2 * DDIM; i += 256) {
        const int dd = i >> 8, k = i & 255;
        W_s[dd * W_STRIDE + k] = W_c[i];
    }
    const float bias = b_c[d];
    __syncthreads();

    const float* wrow = W_s + d * W_STRIDE;
    float4* xr4 = reinterpret_cast<float4*>(xr);
    const float4* xn4 = reinterpret_cast<const float4*>(x_nodes);
    const float4* xi4 = reinterpret_cast<const float4*>(g_xint);

    const int iters = NNODES / NB;
    for (int it = blockIdx.x; it < iters; it += gridDim.x) {
        const int n0 = it * NB;
        for (int idx = t; idx < NB * 64; idx += 256) {
            const int j = idx >> 6, q = idx & 63;
            xr4[idx] = (q < 32) ? xn4[(n0 + j) * 32 + q]
                                : xi4[(n0 + j) * 32 + (q - 32)];
        }
        __syncthreads();

        const float* xrg = xr + grp * 8 * 256;
        float acc[8];
#pragma unroll
        for (int j = 0; j < 8; ++j) acc[j] = bias;

#pragma unroll 4
        for (int k = 0; k < 2 * DDIM; ++k) {
            const float w = wrow[k];
#pragma unroll
            for (int j = 0; j < 8; ++j)
                acc[j] += xrg[j * 256 + k] * w;
        }
#pragma unroll
        for (int j = 0; j < 8; ++j)
            out[(n0 + grp * 8 + j) * DDIM + d] = acc[j];
        __syncthreads();
    }
}

// ---------------------------------------------------------------------------
// Launch. Inputs (metadata order):
//  0 node_type(i32)  1 x_nodes(f32)  2 src(i32)  3 dst(i32)  4 rbf_edges(f32)
//  5 dist(f32)       6 emb(f32)      7 W_e(f32)  8 b_e(f32)  9 W_c(f32) 10 b_c(f32)
// ---------------------------------------------------------------------------
extern "C" void kernel_launch(void* const* d_in, const int* in_sizes, int n_in,
                              void* d_out, int out_size) {
    const int*   node_type = (const int*)  d_in[0];
    const float* x_nodes   = (const float*)d_in[1];
    const int*   src       = (const int*)  d_in[2];
    const int*   dst       = (const int*)  d_in[3];
    const float* rbf       = (const float*)d_in[4];
    const float* dist      = (const float*)d_in[5];
    const float* emb       = (const float*)d_in[6];
    const float* W_e       = (const float*)d_in[7];
    const float* b_e       = (const float*)d_in[8];
    const float* W_c       = (const float*)d_in[9];
    const float* b_c       = (const float*)d_in[10];
    float* out = (float*)d_out;

    int sms = 148;
    cudaDeviceGetAttribute(&sms, cudaDevAttrMultiProcessorCount, 0);

    cudaFuncSetAttribute(fused_edge_kernel,
                         cudaFuncAttributeMaxDynamicSharedMemorySize, EDGE_SMEM);
    cudaFuncSetAttribute(combine_kernel,
                         cudaFuncAttributeMaxDynamicSharedMemorySize,
                         (int)COMBINE_SMEM);

    const int eb = (NEDGES + 511) / 512;  // 1172

    zero_counts_kernel<<<(NNODES + 511) / 512, 512>>>();
    zero_xint_kernel<<<2048, 256>>>();
    hist_kernel<<<eb, 512>>>(dst, src, node_type);
    scan_s1<<<NBLK, 256>>>();
    scan_s2<<<1, 256>>>();
    scan_s3<<<NBLK, 256>>>();
    scatter_sort_kernel<<<eb, 512>>>(dst);
    fused_edge_kernel<<<2 * sms, 256, EDGE_SMEM>>>(rbf, dist, emb, W_e, b_e);
    combine_kernel<<<sms, 256, COMBINE_SMEM>>>(x_nodes, W_c, b_c, out);
}

// round 12
// speedup vs baseline: 3.1900x; 1.1762x over previous
#include <cuda_runtime.h>
#include <cuda_bf16.h>
#include <cstdint>

#define NNODES 50000
#define NEDGES 600000
#define NRBF   50
#define DDIM   128
#define CUTOFF_F 5.0f
#define PI_F 3.14159265358979f
#define NBLK   196   // ceil(50000/256)

// __device__ scratch (no cudaMalloc allowed)
__device__ float g_xint[NNODES * DDIM];    // 25.6 MB segment-sum result
__device__ int   g_count[NNODES];
__device__ int   g_cursor[NNODES];
__device__ int   g_nt[NEDGES];
__device__ int4  g_sedge[NEDGES];          // sorted-by-dst: {eid, dst, nt, 0}
__device__ int   g_bsum[256];
__device__ int   g_bpre[256];

// ---------------------------------------------------------------------------
__device__ __forceinline__ uint32_t smem_u32(const void* p) {
    uint32_t a;
    asm("{ .reg .u64 t; cvta.to.shared.u64 t, %1; cvt.u32.u64 %0, t; }"
        : "=r"(a) : "l"(p));
    return a;
}
__device__ __forceinline__ uint32_t swz128(uint32_t o) { return o ^ ((o >> 3) & 0x70); }

__device__ __forceinline__ void ldmatrix4(uint32_t r[4], uint32_t addr) {
    asm volatile("ldmatrix.sync.aligned.m8n8.x4.shared.b16 {%0,%1,%2,%3}, [%4];"
                 : "=r"(r[0]), "=r"(r[1]), "=r"(r[2]), "=r"(r[3]) : "r"(addr));
}
__device__ __forceinline__ void mma_bf16(float d[4], const uint32_t a[4],
                                         const uint32_t b[2]) {
    asm volatile("mma.sync.aligned.m16n8k16.row.col.f32.bf16.bf16.f32 "
                 "{%0,%1,%2,%3}, {%4,%5,%6,%7}, {%8,%9}, {%0,%1,%2,%3};"
                 : "+f"(d[0]), "+f"(d[1]), "+f"(d[2]), "+f"(d[3])
                 : "r"(a[0]), "r"(a[1]), "r"(a[2]), "r"(a[3]),
                   "r"(b[0]), "r"(b[1]));
}
__device__ __forceinline__ uint32_t pack_bf2(float x, float y) {
    __nv_bfloat162 h = __floats2bfloat162_rn(x, y);
    return *reinterpret_cast<uint32_t*>(&h);
}

// ---------------------------------------------------------------------------
// Zero scratch: g_xint + g_count in one kernel
// ---------------------------------------------------------------------------
__global__ void zero_kernel() {
    int i = blockIdx.x * blockDim.x + threadIdx.x;
    const int n4 = NNODES * DDIM / 4;
    float4* p = reinterpret_cast<float4*>(g_xint);
    float4 z = make_float4(0.f, 0.f, 0.f, 0.f);
    for (int j = i; j < n4; j += gridDim.x * blockDim.x) p[j] = z;
    for (int j = i; j < NNODES; j += gridDim.x * blockDim.x) g_count[j] = 0;
}

// ---------------------------------------------------------------------------
// Sort chain: histogram -> 3-step exclusive scan -> scatter sorted records
// ---------------------------------------------------------------------------
__global__ void hist_kernel(const int* __restrict__ dst,
                            const int* __restrict__ src,
                            const int* __restrict__ node_type) {
    int e = blockIdx.x * blockDim.x + threadIdx.x;
    if (e < NEDGES) {
        atomicAdd(&g_count[dst[e]], 1);
        g_nt[e] = node_type[src[e]];
    }
}

__global__ void scan_s1() {
    __shared__ int sd[256];
    const int b = blockIdx.x, t = threadIdx.x;
    const int i = b * 256 + t;
    sd[t] = (i < NNODES) ? g_count[i] : 0;
    __syncthreads();
    for (int s = 128; s > 0; s >>= 1) {
        if (t < s) sd[t] += sd[t + s];
        __syncthreads();
    }
    if (t == 0) g_bsum[b] = sd[0];
}

__global__ void scan_s2() {
    __shared__ int sc[256];
    const int t = threadIdx.x;
    sc[t] = (t < NBLK) ? g_bsum[t] : 0;
    __syncthreads();
    for (int off = 1; off < 256; off <<= 1) {
        int y = (t >= off) ? sc[t - off] : 0;
        __syncthreads();
        sc[t] += y;
        __syncthreads();
    }
    if (t < NBLK) g_bpre[t] = (t == 0) ? 0 : sc[t - 1];
}

__global__ void scan_s3() {
    __shared__ int sc[256];
    const int b = blockIdx.x, t = threadIdx.x;
    const int i = b * 256 + t;
    const int v = (i < NNODES) ? g_count[i] : 0;
    sc[t] = v;
    __syncthreads();
    for (int off = 1; off < 256; off <<= 1) {
        int y = (t >= off) ? sc[t - off] : 0;
        __syncthreads();
        sc[t] += y;
        __syncthreads();
    }
    if (i < NNODES) g_cursor[i] = g_bpre[b] + sc[t] - v;
}

__global__ void scatter_sort_kernel(const int* __restrict__ dst) {
    int e = blockIdx.x * blockDim.x + threadIdx.x;
    if (e < NEDGES) {
        const int d = dst[e];
        const int idx = atomicAdd(&g_cursor[d], 1);
        g_sedge[idx] = make_int4(e, d, g_nt[e], 0);
    }
}

// ---------------------------------------------------------------------------
// Fused edge kernel (proven): GEMM over sorted edges + segmented reduction +
// per-segment red.global.add.v4.
// ---------------------------------------------------------------------------
#define TILE_E 128
#define MSG_STRIDE 132
#define A_HI_OFF 0
#define A_LO_OFF 16384
#define MSG_OFF  32768
#define CUT_OFF  (MSG_OFF + TILE_E * MSG_STRIDE * 4)
#define EID_OFF  (CUT_OFF + 512)
#define DST_OFF  (EID_OFF + 512)
#define NTS_OFF  (DST_OFF + 512)
#define SEG_OFF  (NTS_OFF + 512)
#define WTOT_OFF (SEG_OFF + 512)
#define EDGE_SMEM (WTOT_OFF + 64)

__device__ __forceinline__ float we_elem(const float* W_e, const float* b_e,
                                         int d, int k) {
    if (k < NRBF) return W_e[d * NRBF + k];
    if (k == NRBF) return b_e[d];
    return 0.f;
}

__global__ __launch_bounds__(256) void fused_edge_kernel(
    const float* __restrict__ rbf,
    const float* __restrict__ dist,
    const float* __restrict__ emb,
    const float* __restrict__ W_e,
    const float* __restrict__ b_e)
{
    extern __shared__ __align__(1024) char smem[];
    const uint32_t sb = smem_u32(smem);
    const int t    = threadIdx.x;
    const int lane = t & 31;
    const int wid  = t >> 5;

    float* msg_s  = reinterpret_cast<float*>(smem + MSG_OFF);
    float* cut_s  = reinterpret_cast<float*>(smem + CUT_OFF);
    int*   eid_s  = reinterpret_cast<int*>(smem + EID_OFF);
    int*   dst_s  = reinterpret_cast<int*>(smem + DST_OFF);
    int*   nts_s  = reinterpret_cast<int*>(smem + NTS_OFF);
    int*   seg_s  = reinterpret_cast<int*>(smem + SEG_OFF);
    int*   wtot_s = reinterpret_cast<int*>(smem + WTOT_OFF);

    {
        uint4* z4 = reinterpret_cast<uint4*>(smem);
        uint4 z = make_uint4(0, 0, 0, 0);
        for (int i = t; i < 32768 / 16; i += 256) z4[i] = z;
    }
    __syncthreads();
    if (t < TILE_E) {
        *reinterpret_cast<uint32_t*>(smem + A_HI_OFF +
            swz128((uint32_t)(t * 128 + 100))) = pack_bf2(1.0f, 0.0f);
    }

    uint32_t Bh[2][4][2], Bl[2][4][2];
#pragma unroll
    for (int n2 = 0; n2 < 2; ++n2) {
        const int d = wid * 16 + n2 * 8 + (lane >> 2);
#pragma unroll
        for (int ks = 0; ks < 4; ++ks) {
            const int k0 = ks * 16 + (lane & 3) * 2;
            float v[4];
            v[0] = we_elem(W_e, b_e, d, k0);
            v[1] = we_elem(W_e, b_e, d, k0 + 1);
            v[2] = we_elem(W_e, b_e, d, k0 + 8);
            v[3] = we_elem(W_e, b_e, d, k0 + 9);
            float h[4];
#pragma unroll
            for (int i = 0; i < 4; ++i)
                h[i] = __bfloat162float(__float2bfloat16_rn(v[i]));
            Bh[n2][ks][0] = pack_bf2(h[0], h[1]);
            Bh[n2][ks][1] = pack_bf2(h[2], h[3]);
            Bl[n2][ks][0] = pack_bf2(v[0] - h[0], v[1] - h[1]);
            Bl[n2][ks][1] = pack_bf2(v[2] - h[2], v[3] - h[3]);
        }
    }
    __syncthreads();

    const int ntiles = (NEDGES + TILE_E - 1) / TILE_E;
    const float4* emb4 = reinterpret_cast<const float4*>(emb);

    for (int tile = blockIdx.x; tile < ntiles; tile += gridDim.x) {
        const int i0 = tile * TILE_E;

        if (t < TILE_E) {
            const int i = i0 + t;
            int e = -1, d = -1, nt = 0;
            float cut = 0.f;
            if (i < NEDGES) {
                const int4 v = g_sedge[i];
                e = v.x; d = v.y; nt = v.z;
                const float dis = dist[e];
                if (dis < CUTOFF_F)
                    cut = 0.5f * (__cosf(dis * (PI_F / CUTOFF_F)) + 1.0f);
            }
            eid_s[t] = e; dst_s[t] = d; nts_s[t] = nt; cut_s[t] = cut;
        }
        __syncthreads();

        for (int idx = t; idx < TILE_E * 25; idx += 256) {
            const int row = idx / 25, p = idx - row * 25;
            const int e = eid_s[row];
            float2 v = make_float2(0.f, 0.f);
            if (e >= 0)
                v = reinterpret_cast<const float2*>(rbf + (size_t)e * NRBF)[p];
            const float hx = __bfloat162float(__float2bfloat16_rn(v.x));
            const float hy = __bfloat162float(__float2bfloat16_rn(v.y));
            const uint32_t sw = swz128((uint32_t)(row * 128 + p * 4));
            *reinterpret_cast<uint32_t*>(smem + A_HI_OFF + sw) = pack_bf2(hx, hy);
            *reinterpret_cast<uint32_t*>(smem + A_LO_OFF + sw) =
                pack_bf2(v.x - hx, v.y - hy);
        }
        __syncthreads();

        const int rowm = lane & 15;
        const int khb  = (lane >> 4) ? 16 : 0;
#pragma unroll 1
        for (int mb = 0; mb < 8; ++mb) {
            uint32_t Ah[4][4], Al[4][4];
            const uint32_t rowbase = (uint32_t)((mb * 16 + rowm) * 128) + khb;
#pragma unroll
            for (int ks = 0; ks < 4; ++ks) {
                const uint32_t off = swz128(rowbase + ks * 32);
                ldmatrix4(Ah[ks], sb + A_HI_OFF + off);
                ldmatrix4(Al[ks], sb + A_LO_OFF + off);
            }
            float D[2][4] = {{0.f, 0.f, 0.f, 0.f}, {0.f, 0.f, 0.f, 0.f}};
#pragma unroll
            for (int n2 = 0; n2 < 2; ++n2) {
#pragma unroll
                for (int ks = 0; ks < 4; ++ks) {
                    mma_bf16(D[n2], Ah[ks], Bh[n2][ks]);
                    mma_bf16(D[n2], Ah[ks], Bl[n2][ks]);
                    mma_bf16(D[n2], Al[ks], Bh[n2][ks]);
                }
            }
            const int g  = lane >> 2, tq = lane & 3;
            const int r0 = mb * 16 + g;
            const float c0 = cut_s[r0], c8 = cut_s[r0 + 8];
#pragma unroll
            for (int n2 = 0; n2 < 2; ++n2) {
                const int col = wid * 16 + n2 * 8 + tq * 2;
                *reinterpret_cast<float2*>(msg_s + r0 * MSG_STRIDE + col) =
                    make_float2(D[n2][0] * c0, D[n2][1] * c0);
                *reinterpret_cast<float2*>(msg_s + (r0 + 8) * MSG_STRIDE + col) =
                    make_float2(D[n2][2] * c8, D[n2][3] * c8);
            }
        }

        int flag = 0;
        if (t < TILE_E)
            flag = (t == 0) || (dst_s[t] != dst_s[t - 1]);
        const unsigned bits = __ballot_sync(0xffffffffu, flag);
        if (t < TILE_E && lane == 0) wtot_s[wid] = __popc(bits);
        __syncthreads();
        if (t < TILE_E) {
            int base = 0;
#pragma unroll
            for (int w = 0; w < 4; ++w) base += (w < wid) ? wtot_s[w] : 0;
            if (flag) {
                const unsigned le = (lane == 31) ? 0xffffffffu
                                                 : ((1u << (lane + 1)) - 1u);
                seg_s[base + __popc(bits & le) - 1] = t;
            }
        }
        __syncthreads();
        const int nseg = wtot_s[0] + wtot_s[1] + wtot_s[2] + wtot_s[3];

        for (int s = wid; s < nseg; s += 8) {
            const int a = seg_s[s];
            const int b = (s + 1 < nseg) ? seg_s[s + 1] : TILE_E;
            const int dv = dst_s[a];
            if (dv < 0) continue;
            float4 acc = make_float4(0.f, 0.f, 0.f, 0.f);
            for (int j = a; j < b; ++j) {
                const float4 m = *reinterpret_cast<const float4*>(
                    msg_s + j * MSG_STRIDE + lane * 4);
                const float4 ev = emb4[(size_t)nts_s[j] * 32 + lane];
                acc.x += m.x * ev.x;
                acc.y += m.y * ev.y;
                acc.z += m.z * ev.z;
                acc.w += m.w * ev.w;
            }
            float* p = g_xint + (size_t)dv * DDIM + lane * 4;
            asm volatile("red.global.add.v4.f32 [%0], {%1, %2, %3, %4};"
                         :: "l"(p), "f"(acc.x), "f"(acc.y),
                            "f"(acc.z), "f"(acc.w) : "memory");
        }
        __syncthreads();
    }
}

// ---------------------------------------------------------------------------
// Combine via mma.sync bf16 3-pass: out[64n x 128d] tile =
//   concat(x_nodes, x_int)[64 x 256] @ W_c^T + b_c.
// A smem: 4 K-chunks of [64 rows x 128B] SW128 atoms, hi/lo (64 KB total).
// B = W_c fragments in registers (2 n2 x 16 ks x 2 regs, hi/lo = 128 regs).
// ---------------------------------------------------------------------------
#define CNB 64
#define CHUNK_B 8192                     // 64 rows * 128 bytes
#define CA_HI 0
#define CA_LO 32768
#define COMBINE_SMEM 65536

__global__ __launch_bounds__(256, 1) void combine_mma_kernel(
    const float* __restrict__ x_nodes,
    const float* __restrict__ W_c,
    const float* __restrict__ b_c,
    float* __restrict__ out)
{
    extern __shared__ __align__(1024) char smem[];
    const uint32_t sb = smem_u32(smem);
    const int t    = threadIdx.x;
    const int lane = t & 31;
    const int wid  = t >> 5;

    // B = W_c hi/lo fragments in registers
    uint32_t Bh[2][16][2], Bl[2][16][2];
#pragma unroll
    for (int n2 = 0; n2 < 2; ++n2) {
        const int d = wid * 16 + n2 * 8 + (lane >> 2);
#pragma unroll
        for (int ks = 0; ks < 16; ++ks) {
            const int k0 = ks * 16 + (lane & 3) * 2;
            float v[4];
            v[0] = W_c[d * 256 + k0];
            v[1] = W_c[d * 256 + k0 + 1];
            v[2] = W_c[d * 256 + k0 + 8];
            v[3] = W_c[d * 256 + k0 + 9];
            float h[4];
#pragma unroll
            for (int i = 0; i < 4; ++i)
                h[i] = __bfloat162float(__float2bfloat16_rn(v[i]));
            Bh[n2][ks][0] = pack_bf2(h[0], h[1]);
            Bh[n2][ks][1] = pack_bf2(h[2], h[3]);
            Bl[n2][ks][0] = pack_bf2(v[0] - h[0], v[1] - h[1]);
            Bl[n2][ks][1] = pack_bf2(v[2] - h[2], v[3] - h[3]);
        }
    }
    // bias for this lane's columns
    float2 bias[2];
#pragma unroll
    for (int n2 = 0; n2 < 2; ++n2) {
        const int col = wid * 16 + n2 * 8 + (lane & 3) * 2;
        bias[n2] = make_float2(b_c[col], b_c[col + 1]);
    }

    const float2* xn2 = reinterpret_cast<const float2*>(x_nodes);
    const float2* xi2 = reinterpret_cast<const float2*>(g_xint);
    const int ntiles = (NNODES + CNB - 1) / CNB;  // 782

    for (int tile = blockIdx.x; tile < ntiles; tile += gridDim.x) {
        const int n0 = tile * CNB;

        // ---- stage A tile: [64 rows x 256 k] hi/lo, chunked SW128 ----
        for (int idx = t; idx < CNB * 128; idx += 256) {
            const int row = idx >> 7, p = idx & 127;   // p = k/2
            const int n = n0 + row;
            float2 v = make_float2(0.f, 0.f);
            if (n < NNODES)
                v = (p < 64) ? xn2[(size_t)n * 64 + p]
                             : xi2[(size_t)n * 64 + (p - 64)];
            const float hx = __bfloat162float(__float2bfloat16_rn(v.x));
            const float hy = __bfloat162float(__float2bfloat16_rn(v.y));
            const uint32_t off = (uint32_t)(p >> 5) * CHUNK_B +
                swz128((uint32_t)(row * 128 + (p & 31) * 4));
            *reinterpret_cast<uint32_t*>(smem + CA_HI + off) = pack_bf2(hx, hy);
            *reinterpret_cast<uint32_t*>(smem + CA_LO + off) =
                pack_bf2(v.x - hx, v.y - hy);
        }
        __syncthreads();

        // ---- MMA: 4 m-blocks of 16 nodes, 16 ksteps, 3 passes ----
        const int rowm = lane & 15;
        const int khb  = (lane >> 4) ? 16 : 0;
#pragma unroll 1
        for (int mb = 0; mb < 4; ++mb) {
            float D[2][4] = {{0.f, 0.f, 0.f, 0.f}, {0.f, 0.f, 0.f, 0.f}};
            const uint32_t rowbase = (uint32_t)((mb * 16 + rowm) * 128) + khb;
#pragma unroll
            for (int ks = 0; ks < 16; ++ks) {
                const uint32_t off = (uint32_t)(ks >> 2) * CHUNK_B +
                    swz128(rowbase + (ks & 3) * 32);
                uint32_t Ah[4], Al[4];
                ldmatrix4(Ah, sb + CA_HI + off);
                ldmatrix4(Al, sb + CA_LO + off);
#pragma unroll
                for (int n2 = 0; n2 < 2; ++n2) {
                    mma_bf16(D[n2], Ah, Bh[n2][ks]);
                    mma_bf16(D[n2], Ah, Bl[n2][ks]);
                    mma_bf16(D[n2], Al, Bh[n2][ks]);
                }
            }
            // ---- epilogue: bias + store ----
            const int g = lane >> 2, tq = lane & 3;
            const int r0 = n0 + mb * 16 + g;
#pragma unroll
            for (int n2 = 0; n2 < 2; ++n2) {
                const int col = wid * 16 + n2 * 8 + tq * 2;
                if (r0 < NNODES)
                    *reinterpret_cast<float2*>(out + (size_t)r0 * DDIM + col) =
                        make_float2(D[n2][0] + bias[n2].x, D[n2][1] + bias[n2].y);
                if (r0 + 8 < NNODES)
                    *reinterpret_cast<float2*>(out + (size_t)(r0 + 8) * DDIM + col) =
                        make_float2(D[n2][2] + bias[n2].x, D[n2][3] + bias[n2].y);
            }
        }
        __syncthreads();
    }
}

// ---------------------------------------------------------------------------
// Launch. Inputs (metadata order):
//  0 node_type(i32)  1 x_nodes(f32)  2 src(i32)  3 dst(i32)  4 rbf_edges(f32)
//  5 dist(f32)       6 emb(f32)      7 W_e(f32)  8 b_e(f32)  9 W_c(f32) 10 b_c(f32)
// ---------------------------------------------------------------------------
extern "C" void kernel_launch(void* const* d_in, const int* in_sizes, int n_in,
                              void* d_out, int out_size) {
    const int*   node_type = (const int*)  d_in[0];
    const float* x_nodes   = (const float*)d_in[1];
    const int*   src       = (const int*)  d_in[2];
    const int*   dst       = (const int*)  d_in[3];
    const float* rbf       = (const float*)d_in[4];
    const float* dist      = (const float*)d_in[5];
    const float* emb       = (const float*)d_in[6];
    const float* W_e       = (const float*)d_in[7];
    const float* b_e       = (const float*)d_in[8];
    const float* W_c       = (const float*)d_in[9];
    const float* b_c       = (const float*)d_in[10];
    float* out = (float*)d_out;

    int sms = 148;
    cudaDeviceGetAttribute(&sms, cudaDevAttrMultiProcessorCount, 0);

    cudaFuncSetAttribute(fused_edge_kernel,
                         cudaFuncAttributeMaxDynamicSharedMemorySize, EDGE_SMEM);
    cudaFuncSetAttribute(combine_mma_kernel,
                         cudaFuncAttributeMaxDynamicSharedMemorySize, COMBINE_SMEM);

    const int eb = (NEDGES + 511) / 512;  // 1172

    zero_kernel<<<2048, 256>>>();
    hist_kernel<<<eb, 512>>>(dst, src, node_type);
    scan_s1<<<NBLK, 256>>>();
    scan_s2<<<1, 256>>>();
    scan_s3<<<NBLK, 256>>>();
    scatter_sort_kernel<<<eb, 512>>>(dst);
    fused_edge_kernel<<<2 * sms, 256, EDGE_SMEM>>>(rbf, dist, emb, W_e, b_e);
    combine_mma_kernel<<<sms, 256, COMBINE_SMEM>>>(x_nodes, W_c, b_c, out);
}